// round 9
// baseline (speedup 1.0000x reference)
#include <cuda_runtime.h>
#include <cstdint>

#define D 128
#define MAXN 50000
#define MAXE 800000

// Scratch (allocation-free): ping-pong H (exact fp32) and Ht (tf32-rounded)
__device__ float g_HA[MAXN * D];
__device__ float g_HB[MAXN * D];
__device__ float g_HtA[MAXN * D];
__device__ float g_HtB[MAXN * D];
__device__ float g_Wt[7 * D * D];     // tf32-rounded weights, transposed [n][k]
__device__ int g_cnt[MAXN];
__device__ int g_row_ptr[MAXN + 1];
__device__ int g_cursor[MAXN];
__device__ int g_adj[MAXE];

// ---------------- helpers ----------------

__device__ __forceinline__ float tf32r(float x) {
    uint32_t u;
    asm("cvt.rna.tf32.f32 %0, %1;" : "=r"(u) : "f"(x));
    return __uint_as_float(u);
}

__device__ __forceinline__ void mma_tf32(float* d,
    uint32_t a0, uint32_t a1, uint32_t a2, uint32_t a3,
    uint32_t b0, uint32_t b1)
{
    asm volatile(
        "mma.sync.aligned.m16n8k8.row.col.f32.tf32.tf32.f32 "
        "{%0,%1,%2,%3}, {%4,%5,%6,%7}, {%8,%9}, {%0,%1,%2,%3};\n"
        : "+f"(d[0]), "+f"(d[1]), "+f"(d[2]), "+f"(d[3])
        : "r"(a0), "r"(a1), "r"(a2), "r"(a3), "r"(b0), "r"(b1));
}

__device__ __forceinline__ void cp_async16(void* smem_p, const void* gmem, bool pred)
{
    uint32_t s = (uint32_t)__cvta_generic_to_shared(smem_p);
    int sz = pred ? 16 : 0;
    asm volatile("cp.async.cg.shared.global [%0], [%1], 16, %2;\n"
                 :: "r"(s), "l"(gmem), "r"(sz));
}
__device__ __forceinline__ void cp_commit() {
    asm volatile("cp.async.commit_group;\n");
}
template <int N_>
__device__ __forceinline__ void cp_wait() {
    asm volatile("cp.async.wait_group %0;\n" :: "n"(N_));
}

// ---------------- conversion ----------------

__global__ void __launch_bounds__(256) convert_w_kernel(
    const float* __restrict__ fw, const float* __restrict__ wrel,
    const float* __restrict__ wroot, float* __restrict__ Wt)
{
    int idx = blockIdx.x * 256 + threadIdx.x;
    if (idx >= 7 * D * D) return;
    int s = idx >> 14;
    int r = idx & 16383;
    int k = r >> 7;
    int n = r & 127;
    const float* srcm = (s == 0) ? fw
                      : (s < 4)  ? wrel + (size_t)(s - 1) * D * D
                                 : wroot + (size_t)(s - 4) * D * D;
    Wt[(size_t)s * D * D + n * D + k] = tf32r(srcm[k * D + n]);
}

// ---------------- CSR build ----------------

__global__ void __launch_bounds__(256) zero_int_kernel(int* __restrict__ p, int n) {
    int i = blockIdx.x * blockDim.x + threadIdx.x;
    for (; i < n; i += gridDim.x * blockDim.x) p[i] = 0;
}

__global__ void __launch_bounds__(256) hist_kernel(
    const int* __restrict__ dst, int* __restrict__ cnt, int E)
{
    int i = blockIdx.x * blockDim.x + threadIdx.x;
    for (; i < E; i += gridDim.x * blockDim.x)
        atomicAdd(&cnt[dst[i]], 1);
}

__global__ void __launch_bounds__(1024) scan_kernel(
    const int* __restrict__ cnt, int* __restrict__ row_ptr,
    int* __restrict__ cursor, int n)
{
    __shared__ int warp_sums[32];
    int tid = threadIdx.x;
    int chunk = (n + 1023) / 1024;
    int beg = tid * chunk;
    int end = min(beg + chunk, n);

    int local = 0;
    for (int i = beg; i < end; i++) local += cnt[i];

    int lane = tid & 31, w = tid >> 5;
    int v = local;
    #pragma unroll
    for (int o = 1; o < 32; o <<= 1) {
        int t = __shfl_up_sync(~0u, v, o);
        if (lane >= o) v += t;
    }
    if (lane == 31) warp_sums[w] = v;
    __syncthreads();
    if (w == 0) {
        int s = warp_sums[lane];
        #pragma unroll
        for (int o = 1; o < 32; o <<= 1) {
            int t = __shfl_up_sync(~0u, s, o);
            if (lane >= o) s += t;
        }
        warp_sums[lane] = s;
    }
    __syncthreads();

    int excl = v - local + (w > 0 ? warp_sums[w - 1] : 0);
    int run = excl;
    for (int i = beg; i < end; i++) {
        row_ptr[i] = run;
        cursor[i]  = run;
        run += cnt[i];
    }
    if (tid == 1023) row_ptr[n] = run;
}

__global__ void __launch_bounds__(256) fill_kernel(
    const int* __restrict__ src, const int* __restrict__ dst,
    int* __restrict__ cursor, int* __restrict__ adj, int E)
{
    int i = blockIdx.x * blockDim.x + threadIdx.x;
    for (; i < E; i += gridDim.x * blockDim.x) {
        int p = atomicAdd(&cursor[dst[i]], 1);
        adj[p] = src[i];
    }
}

// ---------------- in_fc GEMM (tf32, A from global, double-buffered) ------

#define SK 36
#define TILE_F (128 * SK)
#define STAGE_F (2 * TILE_F)
#define GEMM_SMEM (2 * STAGE_F * 4)

__global__ void __launch_bounds__(256, 2) gemm_infc(
    const float* __restrict__ A1, const float* __restrict__ W1,
    const float* __restrict__ bias,
    float* __restrict__ out, float* __restrict__ OutRt, int N)
{
    extern __shared__ __align__(16) float sm[];

    int tid = threadIdx.x;
    int lane = tid & 31, w = tid >> 5;
    int warp_m = w & 3;
    int warp_n = w >> 2;
    int g = lane >> 2, tg = lane & 3;
    int row0 = blockIdx.x * 128;

    float acc[2][8][4];
    #pragma unroll
    for (int mf = 0; mf < 2; mf++)
        #pragma unroll
        for (int nf = 0; nf < 8; nf++)
            #pragma unroll
            for (int c = 0; c < 4; c++) acc[mf][nf][c] = 0.f;

    auto prefetch = [&](int c, int buf) {
        int koff = c * 32;
        float* base = sm + buf * STAGE_F;
        #pragma unroll
        for (int i = 0; i < 4; i++) {
            int idx = tid + i * 256;
            int r = idx >> 3, u = idx & 7;
            int gr = row0 + r;
            cp_async16(base + r * SK + u * 4,
                       A1 + (size_t)gr * D + koff + u * 4, gr < N);
            cp_async16(base + TILE_F + r * SK + u * 4,
                       W1 + (size_t)r * D + koff + u * 4, true);
        }
        cp_commit();
    };

    prefetch(0, 0);

    #pragma unroll 1
    for (int c = 0; c < 4; c++) {
        cp_wait<0>();
        __syncthreads();
        if (c + 1 < 4) prefetch(c + 1, (c + 1) & 1);

        const float* sa = sm + (c & 1) * STAGE_F;
        const float* sb = sa + TILE_F;

        #pragma unroll
        for (int ks = 0; ks < 4; ks++) {
            uint32_t bfr[8][2];
            #pragma unroll
            for (int nf = 0; nf < 8; nf++) {
                int n = warp_n * 64 + nf * 8 + g;
                bfr[nf][0] = __float_as_uint(sb[n * SK + ks * 8 + tg]);
                bfr[nf][1] = __float_as_uint(sb[n * SK + ks * 8 + tg + 4]);
            }
            #pragma unroll
            for (int mf = 0; mf < 2; mf++) {
                int r0 = warp_m * 32 + mf * 16 + g;
                uint32_t a0 = __float_as_uint(sa[r0 * SK + ks * 8 + tg]);
                uint32_t a1 = __float_as_uint(sa[(r0 + 8) * SK + ks * 8 + tg]);
                uint32_t a2 = __float_as_uint(sa[r0 * SK + ks * 8 + tg + 4]);
                uint32_t a3 = __float_as_uint(sa[(r0 + 8) * SK + ks * 8 + tg + 4]);
                #pragma unroll
                for (int nf = 0; nf < 8; nf++)
                    mma_tf32(acc[mf][nf], a0, a1, a2, a3,
                             bfr[nf][0], bfr[nf][1]);
            }
        }
    }

    __syncthreads();

    #pragma unroll
    for (int mf = 0; mf < 2; mf++) {
        #pragma unroll
        for (int half = 0; half < 2; half++) {
            int row = row0 + warp_m * 32 + mf * 16 + g + half * 8;
            if (row >= N) continue;
            #pragma unroll
            for (int nf = 0; nf < 8; nf++) {
                int col = warp_n * 64 + nf * 8 + tg * 2;
                float cx = acc[mf][nf][half * 2 + 0] + __ldg(bias + col);
                float cy = acc[mf][nf][half * 2 + 1] + __ldg(bias + col + 1);
                *(float2*)(out + (size_t)row * D + col) = make_float2(cx, cy);
                *(float2*)(OutRt + (size_t)row * D + col) =
                    make_float2(tf32r(cx), tf32r(cy));
            }
        }
    }
}

// ---------------- fused layer: gather-aggregate + dual GEMM ----------------
// smem: AGG tile 128x132 f32 (66KB, tf32-rounded) + single-stage A2 chunk
// (128x36 f32) + single-stage B chunk = 102KB -> 2 blocks/SM. Co-resident
// block overlaps gather (LTS) with the other block's MMA (tensor).
// K-loop: 8 chunks of 32 (c<4: term rel, A=sAGG; c>=4: term root, A=Ht staged).

#define SKA 132
#define AGG_F (128 * SKA)
#define CH_F  (128 * SK)
#define FUSED_SMEM ((AGG_F + 2 * CH_F) * 4)   // 104448 B

template <bool LAST>
__global__ void __launch_bounds__(256, 2) fused_layer(
    const int* __restrict__ row_ptr, const int* __restrict__ adj,
    const float* __restrict__ Hin, const float* __restrict__ Htin,
    const float* __restrict__ W1, const float* __restrict__ W2,
    const float* __restrict__ bias,
    float* __restrict__ Hout, float* __restrict__ Htout, int N)
{
    extern __shared__ __align__(16) float sm[];
    float* sAgg = sm;                 // [128][SKA]
    float* sA2  = sm + AGG_F;         // [128][SK]
    float* sB   = sA2 + CH_F;         // [128][SK]

    int tid = threadIdx.x;
    int lane = tid & 31, w = tid >> 5;
    int warp_m = w & 3;
    int warp_n = w >> 2;
    int g = lane >> 2, tg = lane & 3;
    int row0 = blockIdx.x * 128;

    // ---- stage B chunk 0 early (independent of gather) ----
    auto prefetch = [&](int c) {
        int term = c >> 2;
        int koff = (c & 3) * 32;
        const float* Bg = term ? W2 : W1;
        #pragma unroll
        for (int i = 0; i < 4; i++) {
            int idx = tid + i * 256;
            int r = idx >> 3, u = idx & 7;
            cp_async16(sB + r * SK + u * 4, Bg + (size_t)r * D + koff + u * 4, true);
            if (term) {
                int gr = row0 + r;
                cp_async16(sA2 + r * SK + u * 4,
                           Htin + (size_t)gr * D + koff + u * 4, gr < N);
            }
        }
        cp_commit();
    };

    prefetch(0);

    // ---- gather phase: warp w owns rows w*16 .. w*16+15 ----
    #pragma unroll 1
    for (int i = 0; i < 16; i++) {
        int r = w * 16 + i;
        int node = row0 + r;
        float4 acc = make_float4(0.f, 0.f, 0.f, 0.f);
        if (node < N) {
            int beg = __ldg(row_ptr + node);
            int end = __ldg(row_ptr + node + 1);
            int e = beg;
            for (; e + 4 <= end; e += 4) {
                int s0 = __ldg(adj + e + 0);
                int s1 = __ldg(adj + e + 1);
                int s2 = __ldg(adj + e + 2);
                int s3 = __ldg(adj + e + 3);
                float4 v0 = __ldg((const float4*)(Hin + (size_t)s0 * D) + lane);
                float4 v1 = __ldg((const float4*)(Hin + (size_t)s1 * D) + lane);
                float4 v2 = __ldg((const float4*)(Hin + (size_t)s2 * D) + lane);
                float4 v3 = __ldg((const float4*)(Hin + (size_t)s3 * D) + lane);
                acc.x += v0.x + v1.x + v2.x + v3.x;
                acc.y += v0.y + v1.y + v2.y + v3.y;
                acc.z += v0.z + v1.z + v2.z + v3.z;
                acc.w += v0.w + v1.w + v2.w + v3.w;
            }
            for (; e < end; e++) {
                int s = __ldg(adj + e);
                float4 v = __ldg((const float4*)(Hin + (size_t)s * D) + lane);
                acc.x += v.x; acc.y += v.y; acc.z += v.z; acc.w += v.w;
            }
            acc.x = tf32r(acc.x); acc.y = tf32r(acc.y);
            acc.z = tf32r(acc.z); acc.w = tf32r(acc.w);
        }
        *(float4*)&sAgg[r * SKA + lane * 4] = acc;
    }

    float acc[2][8][4];
    #pragma unroll
    for (int mf = 0; mf < 2; mf++)
        #pragma unroll
        for (int nf = 0; nf < 8; nf++)
            #pragma unroll
            for (int c = 0; c < 4; c++) acc[mf][nf][c] = 0.f;

    // ---- K loop: 8 chunks ----
    #pragma unroll 1
    for (int c = 0; c < 8; c++) {
        cp_wait<0>();
        __syncthreads();             // stage ready + (c=0) sAgg visible

        int term = c >> 2;
        int coloff = term ? 0 : (c & 3) * 32;
        const float* sa = term ? sA2 : sAgg;
        int astride = term ? SK : SKA;

        #pragma unroll
        for (int ks = 0; ks < 4; ks++) {
            uint32_t bfr[8][2];
            #pragma unroll
            for (int nf = 0; nf < 8; nf++) {
                int n = warp_n * 64 + nf * 8 + g;
                bfr[nf][0] = __float_as_uint(sB[n * SK + ks * 8 + tg]);
                bfr[nf][1] = __float_as_uint(sB[n * SK + ks * 8 + tg + 4]);
            }
            #pragma unroll
            for (int mf = 0; mf < 2; mf++) {
                int r0 = warp_m * 32 + mf * 16 + g;
                uint32_t a0 = __float_as_uint(sa[r0 * astride + coloff + ks * 8 + tg]);
                uint32_t a1 = __float_as_uint(sa[(r0 + 8) * astride + coloff + ks * 8 + tg]);
                uint32_t a2 = __float_as_uint(sa[r0 * astride + coloff + ks * 8 + tg + 4]);
                uint32_t a3 = __float_as_uint(sa[(r0 + 8) * astride + coloff + ks * 8 + tg + 4]);
                #pragma unroll
                for (int nf = 0; nf < 8; nf++)
                    mma_tf32(acc[mf][nf], a0, a1, a2, a3,
                             bfr[nf][0], bfr[nf][1]);
            }
        }

        __syncthreads();             // all reads of sA2/sB done
        if (c + 1 < 8) prefetch(c + 1);
    }

    // ---- epilogue ----
    #pragma unroll
    for (int mf = 0; mf < 2; mf++) {
        #pragma unroll
        for (int half = 0; half < 2; half++) {
            int row = row0 + warp_m * 32 + mf * 16 + g + half * 8;
            if (row >= N) continue;
            #pragma unroll
            for (int nf = 0; nf < 8; nf++) {
                int col = warp_n * 64 + nf * 8 + tg * 2;
                float cx = acc[mf][nf][half * 2 + 0] + __ldg(bias + col);
                float cy = acc[mf][nf][half * 2 + 1] + __ldg(bias + col + 1);
                float2 h2 = *(const float2*)(Hin + (size_t)row * D + col);
                cx = fmaxf(cx, 0.f) + h2.x;
                cy = fmaxf(cy, 0.f) + h2.y;
                *(float2*)(Hout + (size_t)row * D + col) = make_float2(cx, cy);
                if (!LAST) {
                    *(float2*)(Htout + (size_t)row * D + col) =
                        make_float2(tf32r(cx), tf32r(cy));
                }
            }
        }
    }
}

// ---------------- launch ----------------

extern "C" void kernel_launch(void* const* d_in, const int* in_sizes, int n_in,
                              void* d_out, int out_size)
{
    const float* x       = (const float*)d_in[0];
    const int*   ei      = (const int*)  d_in[1];
    const float* in_fc_w = (const float*)d_in[2];
    const float* in_fc_b = (const float*)d_in[3];
    const float* w_rel   = (const float*)d_in[4];
    const float* b_rel   = (const float*)d_in[5];
    const float* w_root  = (const float*)d_in[6];

    int N = in_sizes[0] / D;
    int E = in_sizes[1] / 2;
    const int* src = ei;
    const int* dst = ei + E;

    float *HA, *HB, *HtA, *HtB, *Wt;
    int *cnt, *row_ptr, *cursor, *adj;
    cudaGetSymbolAddress((void**)&HA,      g_HA);
    cudaGetSymbolAddress((void**)&HB,      g_HB);
    cudaGetSymbolAddress((void**)&HtA,     g_HtA);
    cudaGetSymbolAddress((void**)&HtB,     g_HtB);
    cudaGetSymbolAddress((void**)&Wt,      g_Wt);
    cudaGetSymbolAddress((void**)&cnt,     g_cnt);
    cudaGetSymbolAddress((void**)&row_ptr, g_row_ptr);
    cudaGetSymbolAddress((void**)&cursor,  g_cursor);
    cudaGetSymbolAddress((void**)&adj,     g_adj);

    cudaFuncSetAttribute(gemm_infc,
        cudaFuncAttributeMaxDynamicSharedMemorySize, GEMM_SMEM);
    cudaFuncSetAttribute(fused_layer<false>,
        cudaFuncAttributeMaxDynamicSharedMemorySize, FUSED_SMEM);
    cudaFuncSetAttribute(fused_layer<true>,
        cudaFuncAttributeMaxDynamicSharedMemorySize, FUSED_SMEM);

    int gblocks = (N + 127) / 128;
    int eblocks = (E + 255) / 256;

    convert_w_kernel<<<(7 * D * D + 255) / 256, 256>>>(in_fc_w, w_rel, w_root, Wt);

    // CSR build (dst-sorted adjacency)
    zero_int_kernel<<<(N + 255) / 256, 256>>>(cnt, N);
    hist_kernel<<<eblocks, 256>>>(dst, cnt, E);
    scan_kernel<<<1, 1024>>>(cnt, row_ptr, cursor, N);
    fill_kernel<<<eblocks, 256>>>(src, dst, cursor, adj, E);

    // h = x @ in_fc_w + in_fc_b  (x fed raw; mma truncates to tf32)
    gemm_infc<<<gblocks, 256, GEMM_SMEM>>>(x, Wt, in_fc_b, HA, HtA, N);

    // layer 0: HA -> HB
    fused_layer<false><<<gblocks, 256, FUSED_SMEM>>>(
        row_ptr, adj, HA, HtA,
        Wt + (size_t)1 * D * D, Wt + (size_t)4 * D * D,
        b_rel + 0 * D, HB, HtB, N);
    // layer 1: HB -> HA
    fused_layer<false><<<gblocks, 256, FUSED_SMEM>>>(
        row_ptr, adj, HB, HtB,
        Wt + (size_t)2 * D * D, Wt + (size_t)5 * D * D,
        b_rel + 1 * D, HA, HtA, N);
    // layer 2: HA -> d_out
    fused_layer<true><<<gblocks, 256, FUSED_SMEM>>>(
        row_ptr, adj, HA, HtA,
        Wt + (size_t)3 * D * D, Wt + (size_t)6 * D * D,
        b_rel + 2 * D, (float*)d_out, nullptr, N);
}

// round 10
// speedup vs baseline: 1.9615x; 1.9615x over previous
#include <cuda_runtime.h>
#include <cstdint>

#define D 128
#define MAXN 50000
#define MAXE 800000

// Scratch (allocation-free)
__device__ float g_H[MAXN * D];       // exact fp32 residual H
__device__ float g_Ht[MAXN * D];      // tf32-rounded H (root-term operand)
__device__ float g_AGG[MAXN * D];     // tf32-rounded agg
__device__ float g_Wt[7 * D * D];     // tf32-rounded weights, transposed [n][k]
__device__ int g_cnt[MAXN];
__device__ int g_row_ptr[MAXN + 1];
__device__ int g_cursor[MAXN];
__device__ int g_adj[MAXE];
__device__ int g_bsum[64];
__device__ int g_bofs[64];

// ---------------- helpers ----------------

__device__ __forceinline__ float tf32r(float x) {
    uint32_t u;
    asm("cvt.rna.tf32.f32 %0, %1;" : "=r"(u) : "f"(x));
    return __uint_as_float(u);
}

__device__ __forceinline__ void mma_tf32(float* d,
    uint32_t a0, uint32_t a1, uint32_t a2, uint32_t a3,
    uint32_t b0, uint32_t b1)
{
    asm volatile(
        "mma.sync.aligned.m16n8k8.row.col.f32.tf32.tf32.f32 "
        "{%0,%1,%2,%3}, {%4,%5,%6,%7}, {%8,%9}, {%0,%1,%2,%3};\n"
        : "+f"(d[0]), "+f"(d[1]), "+f"(d[2]), "+f"(d[3])
        : "r"(a0), "r"(a1), "r"(a2), "r"(a3), "r"(b0), "r"(b1));
}

__device__ __forceinline__ void cp_async16(void* smem_p, const void* gmem, bool pred)
{
    uint32_t s = (uint32_t)__cvta_generic_to_shared(smem_p);
    int sz = pred ? 16 : 0;
    asm volatile("cp.async.cg.shared.global [%0], [%1], 16, %2;\n"
                 :: "r"(s), "l"(gmem), "r"(sz));
}
__device__ __forceinline__ void cp_commit() {
    asm volatile("cp.async.commit_group;\n");
}
template <int N_>
__device__ __forceinline__ void cp_wait() {
    asm volatile("cp.async.wait_group %0;\n" :: "n"(N_));
}

// ---------------- conversion ----------------

__global__ void __launch_bounds__(256) convert_w_kernel(
    const float* __restrict__ fw, const float* __restrict__ wrel,
    const float* __restrict__ wroot, float* __restrict__ Wt)
{
    int idx = blockIdx.x * 256 + threadIdx.x;
    if (idx >= 7 * D * D) return;
    int s = idx >> 14;
    int r = idx & 16383;
    int k = r >> 7;
    int n = r & 127;
    const float* srcm = (s == 0) ? fw
                      : (s < 4)  ? wrel + (size_t)(s - 1) * D * D
                                 : wroot + (size_t)(s - 4) * D * D;
    Wt[(size_t)s * D * D + n * D + k] = tf32r(srcm[k * D + n]);
}

// ---------------- CSR build ----------------

__global__ void __launch_bounds__(256) zero_int_kernel(int* __restrict__ p, int n) {
    int i = blockIdx.x * blockDim.x + threadIdx.x;
    for (; i < n; i += gridDim.x * blockDim.x) p[i] = 0;
}

__global__ void __launch_bounds__(256) hist_kernel(
    const int* __restrict__ dst, int* __restrict__ cnt, int E)
{
    int i = blockIdx.x * blockDim.x + threadIdx.x;
    for (; i < E; i += gridDim.x * blockDim.x)
        atomicAdd(&cnt[dst[i]], 1);
}

// Phase 1: per-block exclusive scan of 1024 counters; write local excl to
// row_ptr and block total to bsum.
__global__ void __launch_bounds__(1024) scan1_kernel(
    const int* __restrict__ cnt, int* __restrict__ row_ptr,
    int* __restrict__ bsum, int n)
{
    __shared__ int warp_sums[32];
    int tid = threadIdx.x;
    int i = blockIdx.x * 1024 + tid;
    int lane = tid & 31, w = tid >> 5;

    int v = (i < n) ? cnt[i] : 0;
    int incl = v;
    #pragma unroll
    for (int o = 1; o < 32; o <<= 1) {
        int t = __shfl_up_sync(~0u, incl, o);
        if (lane >= o) incl += t;
    }
    if (lane == 31) warp_sums[w] = incl;
    __syncthreads();
    if (w == 0) {
        int s = warp_sums[lane];
        #pragma unroll
        for (int o = 1; o < 32; o <<= 1) {
            int t = __shfl_up_sync(~0u, s, o);
            if (lane >= o) s += t;
        }
        warp_sums[lane] = s;
    }
    __syncthreads();

    int excl = incl - v + (w > 0 ? warp_sums[w - 1] : 0);
    if (i < n) row_ptr[i] = excl;
    if (tid == 1023) bsum[blockIdx.x] = excl + v;
}

// Phase 2: single warp scans block sums -> exclusive offsets; writes row_ptr[n].
__global__ void __launch_bounds__(64) scan2_kernel(
    const int* __restrict__ bsum, int* __restrict__ bofs,
    int* __restrict__ row_ptr, int nblocks, int n)
{
    int tid = threadIdx.x;
    int v = (tid < nblocks) ? bsum[tid] : 0;
    int incl = v;
    #pragma unroll
    for (int o = 1; o < 64; o <<= 1) {
        int t = __shfl_up_sync(~0u, incl & 0x7FFFFFFF, o);   // 64>32: do two-warp manually
        (void)t;
        break;
    }
    // simple serial scan by thread 0 (64 elements, trivial)
    __shared__ int sh[64];
    sh[tid] = v;
    __syncthreads();
    if (tid == 0) {
        int run = 0;
        for (int b = 0; b < nblocks; b++) {
            bofs[b] = run;
            run += sh[b];
        }
        row_ptr[n] = run;
    }
}

// Phase 3: add block offsets; copy to cursor.
__global__ void __launch_bounds__(1024) scan3_kernel(
    int* __restrict__ row_ptr, int* __restrict__ cursor,
    const int* __restrict__ bofs, int n)
{
    int i = blockIdx.x * 1024 + threadIdx.x;
    if (i >= n) return;
    int v = row_ptr[i] + bofs[blockIdx.x];
    row_ptr[i] = v;
    cursor[i] = v;
}

__global__ void __launch_bounds__(256) fill_kernel(
    const int* __restrict__ src, const int* __restrict__ dst,
    int* __restrict__ cursor, int* __restrict__ adj, int E)
{
    int i = blockIdx.x * blockDim.x + threadIdx.x;
    for (; i < E; i += gridDim.x * blockDim.x) {
        int p = atomicAdd(&cursor[dst[i]], 1);
        adj[p] = src[i];
    }
}

// ---------------- gather-aggregate -> tf32-rounded fp32 ----------------

__global__ void __launch_bounds__(256) aggregate_kernel(
    const float* __restrict__ H, const int* __restrict__ row_ptr,
    const int* __restrict__ adj, float* __restrict__ AGG, int N)
{
    int node = (blockIdx.x * blockDim.x + threadIdx.x) >> 5;
    int lane = threadIdx.x & 31;
    if (node >= N) return;
    int beg = __ldg(row_ptr + node);
    int end = __ldg(row_ptr + node + 1);

    float4 acc = make_float4(0.f, 0.f, 0.f, 0.f);
    int e = beg;
    for (; e + 4 <= end; e += 4) {
        int s0 = __ldg(adj + e + 0);
        int s1 = __ldg(adj + e + 1);
        int s2 = __ldg(adj + e + 2);
        int s3 = __ldg(adj + e + 3);
        float4 v0 = __ldg((const float4*)(H + (size_t)s0 * D) + lane);
        float4 v1 = __ldg((const float4*)(H + (size_t)s1 * D) + lane);
        float4 v2 = __ldg((const float4*)(H + (size_t)s2 * D) + lane);
        float4 v3 = __ldg((const float4*)(H + (size_t)s3 * D) + lane);
        acc.x += v0.x + v1.x + v2.x + v3.x;
        acc.y += v0.y + v1.y + v2.y + v3.y;
        acc.z += v0.z + v1.z + v2.z + v3.z;
        acc.w += v0.w + v1.w + v2.w + v3.w;
    }
    for (; e < end; e++) {
        int s = __ldg(adj + e);
        float4 v = __ldg((const float4*)(H + (size_t)s * D) + lane);
        acc.x += v.x; acc.y += v.y; acc.z += v.z; acc.w += v.w;
    }
    acc.x = tf32r(acc.x); acc.y = tf32r(acc.y);
    acc.z = tf32r(acc.z); acc.w = tf32r(acc.w);
    ((float4*)(AGG + (size_t)node * D))[lane] = acc;
}

// ---------------- tf32 GEMM kernels (R8-proven) ----------------

#define SK 36
#define TILE_F (128 * SK)
#define STAGE_F (2 * TILE_F)
#define GEMM_SMEM (2 * STAGE_F * 4)

// in_fc: A = raw x from global (tf32 conversion implicit in mma), single GEMM.
__global__ void __launch_bounds__(256, 2) gemm_infc(
    const float* __restrict__ A1, const float* __restrict__ W1,
    const float* __restrict__ bias,
    float* __restrict__ out, float* __restrict__ OutRt, int N)
{
    extern __shared__ __align__(16) float sm[];

    int tid = threadIdx.x;
    int lane = tid & 31, w = tid >> 5;
    int warp_m = w & 3;
    int warp_n = w >> 2;
    int g = lane >> 2, tg = lane & 3;
    int row0 = blockIdx.x * 128;

    float acc[2][8][4];
    #pragma unroll
    for (int mf = 0; mf < 2; mf++)
        #pragma unroll
        for (int nf = 0; nf < 8; nf++)
            #pragma unroll
            for (int c = 0; c < 4; c++) acc[mf][nf][c] = 0.f;

    auto prefetch = [&](int c, int buf) {
        int koff = c * 32;
        float* base = sm + buf * STAGE_F;
        #pragma unroll
        for (int i = 0; i < 4; i++) {
            int idx = tid + i * 256;
            int r = idx >> 3, u = idx & 7;
            int gr = row0 + r;
            cp_async16(base + r * SK + u * 4,
                       A1 + (size_t)gr * D + koff + u * 4, gr < N);
            cp_async16(base + TILE_F + r * SK + u * 4,
                       W1 + (size_t)r * D + koff + u * 4, true);
        }
        cp_commit();
    };

    prefetch(0, 0);

    #pragma unroll 1
    for (int c = 0; c < 4; c++) {
        cp_wait<0>();
        __syncthreads();
        if (c + 1 < 4) prefetch(c + 1, (c + 1) & 1);

        const float* sa = sm + (c & 1) * STAGE_F;
        const float* sb = sa + TILE_F;

        #pragma unroll
        for (int ks = 0; ks < 4; ks++) {
            uint32_t bfr[8][2];
            #pragma unroll
            for (int nf = 0; nf < 8; nf++) {
                int n = warp_n * 64 + nf * 8 + g;
                bfr[nf][0] = __float_as_uint(sb[n * SK + ks * 8 + tg]);
                bfr[nf][1] = __float_as_uint(sb[n * SK + ks * 8 + tg + 4]);
            }
            #pragma unroll
            for (int mf = 0; mf < 2; mf++) {
                int r0 = warp_m * 32 + mf * 16 + g;
                uint32_t a0 = __float_as_uint(sa[r0 * SK + ks * 8 + tg]);
                uint32_t a1 = __float_as_uint(sa[(r0 + 8) * SK + ks * 8 + tg]);
                uint32_t a2 = __float_as_uint(sa[r0 * SK + ks * 8 + tg + 4]);
                uint32_t a3 = __float_as_uint(sa[(r0 + 8) * SK + ks * 8 + tg + 4]);
                #pragma unroll
                for (int nf = 0; nf < 8; nf++)
                    mma_tf32(acc[mf][nf], a0, a1, a2, a3,
                             bfr[nf][0], bfr[nf][1]);
            }
        }
    }

    __syncthreads();

    #pragma unroll
    for (int mf = 0; mf < 2; mf++) {
        #pragma unroll
        for (int half = 0; half < 2; half++) {
            int row = row0 + warp_m * 32 + mf * 16 + g + half * 8;
            if (row >= N) continue;
            #pragma unroll
            for (int nf = 0; nf < 8; nf++) {
                int col = warp_n * 64 + nf * 8 + tg * 2;
                float cx = acc[mf][nf][half * 2 + 0] + __ldg(bias + col);
                float cy = acc[mf][nf][half * 2 + 1] + __ldg(bias + col + 1);
                *(float2*)(out + (size_t)row * D + col) = make_float2(cx, cy);
                *(float2*)(OutRt + (size_t)row * D + col) =
                    make_float2(tf32r(cx), tf32r(cy));
            }
        }
    }
}

// dual-term layer GEMM: relu(AGG@W1 + Ht@W2 + bias) + H, out fp32 (+ rounded copy)
template <bool WRITE_RT>
__global__ void __launch_bounds__(256, 2) gemm_tf32(
    const float* __restrict__ A1, const float* __restrict__ W1,
    const float* __restrict__ A2, const float* __restrict__ W2,
    const float* __restrict__ bias, const float* __restrict__ Hres,
    float* __restrict__ out, float* __restrict__ OutRt, int N)
{
    extern __shared__ __align__(16) float sm[];

    int tid = threadIdx.x;
    int lane = tid & 31, w = tid >> 5;
    int warp_m = w & 3;
    int warp_n = w >> 2;
    int g = lane >> 2, tg = lane & 3;
    int row0 = blockIdx.x * 128;

    float acc[2][8][4];
    #pragma unroll
    for (int mf = 0; mf < 2; mf++)
        #pragma unroll
        for (int nf = 0; nf < 8; nf++)
            #pragma unroll
            for (int c = 0; c < 4; c++) acc[mf][nf][c] = 0.f;

    auto prefetch = [&](int c, int buf) {
        int t = c >> 2;
        int koff = (c & 3) * 32;
        const float* Ag = t ? A2 : A1;
        const float* Bg = t ? W2 : W1;
        float* base = sm + buf * STAGE_F;
        #pragma unroll
        for (int i = 0; i < 4; i++) {
            int idx = tid + i * 256;
            int r = idx >> 3, u = idx & 7;
            int gr = row0 + r;
            cp_async16(base + r * SK + u * 4,
                       Ag + (size_t)gr * D + koff + u * 4, gr < N);
            cp_async16(base + TILE_F + r * SK + u * 4,
                       Bg + (size_t)r * D + koff + u * 4, true);
        }
        cp_commit();
    };

    prefetch(0, 0);

    #pragma unroll 1
    for (int c = 0; c < 8; c++) {
        cp_wait<0>();
        __syncthreads();
        if (c + 1 < 8) prefetch(c + 1, (c + 1) & 1);

        const float* sa = sm + (c & 1) * STAGE_F;
        const float* sb = sa + TILE_F;

        #pragma unroll
        for (int ks = 0; ks < 4; ks++) {
            uint32_t bfr[8][2];
            #pragma unroll
            for (int nf = 0; nf < 8; nf++) {
                int n = warp_n * 64 + nf * 8 + g;
                bfr[nf][0] = __float_as_uint(sb[n * SK + ks * 8 + tg]);
                bfr[nf][1] = __float_as_uint(sb[n * SK + ks * 8 + tg + 4]);
            }
            #pragma unroll
            for (int mf = 0; mf < 2; mf++) {
                int r0 = warp_m * 32 + mf * 16 + g;
                uint32_t a0 = __float_as_uint(sa[r0 * SK + ks * 8 + tg]);
                uint32_t a1 = __float_as_uint(sa[(r0 + 8) * SK + ks * 8 + tg]);
                uint32_t a2 = __float_as_uint(sa[r0 * SK + ks * 8 + tg + 4]);
                uint32_t a3 = __float_as_uint(sa[(r0 + 8) * SK + ks * 8 + tg + 4]);
                #pragma unroll
                for (int nf = 0; nf < 8; nf++)
                    mma_tf32(acc[mf][nf], a0, a1, a2, a3,
                             bfr[nf][0], bfr[nf][1]);
            }
        }
    }

    __syncthreads();

    #pragma unroll
    for (int mf = 0; mf < 2; mf++) {
        #pragma unroll
        for (int half = 0; half < 2; half++) {
            int row = row0 + warp_m * 32 + mf * 16 + g + half * 8;
            if (row >= N) continue;
            #pragma unroll
            for (int nf = 0; nf < 8; nf++) {
                int col = warp_n * 64 + nf * 8 + tg * 2;
                float cx = acc[mf][nf][half * 2 + 0] + __ldg(bias + col);
                float cy = acc[mf][nf][half * 2 + 1] + __ldg(bias + col + 1);
                float2 h2 = *(const float2*)(Hres + (size_t)row * D + col);
                cx = fmaxf(cx, 0.f) + h2.x;
                cy = fmaxf(cy, 0.f) + h2.y;
                *(float2*)(out + (size_t)row * D + col) = make_float2(cx, cy);
                if (WRITE_RT) {
                    *(float2*)(OutRt + (size_t)row * D + col) =
                        make_float2(tf32r(cx), tf32r(cy));
                }
            }
        }
    }
}

// ---------------- launch ----------------

extern "C" void kernel_launch(void* const* d_in, const int* in_sizes, int n_in,
                              void* d_out, int out_size)
{
    const float* x       = (const float*)d_in[0];
    const int*   ei      = (const int*)  d_in[1];
    const float* in_fc_w = (const float*)d_in[2];
    const float* in_fc_b = (const float*)d_in[3];
    const float* w_rel   = (const float*)d_in[4];
    const float* b_rel   = (const float*)d_in[5];
    const float* w_root  = (const float*)d_in[6];

    int N = in_sizes[0] / D;
    int E = in_sizes[1] / 2;
    const int* src = ei;
    const int* dst = ei + E;

    float *H, *Ht, *AGG, *Wt;
    int *cnt, *row_ptr, *cursor, *adj, *bsum, *bofs;
    cudaGetSymbolAddress((void**)&H,       g_H);
    cudaGetSymbolAddress((void**)&Ht,      g_Ht);
    cudaGetSymbolAddress((void**)&AGG,     g_AGG);
    cudaGetSymbolAddress((void**)&Wt,      g_Wt);
    cudaGetSymbolAddress((void**)&cnt,     g_cnt);
    cudaGetSymbolAddress((void**)&row_ptr, g_row_ptr);
    cudaGetSymbolAddress((void**)&cursor,  g_cursor);
    cudaGetSymbolAddress((void**)&adj,     g_adj);
    cudaGetSymbolAddress((void**)&bsum,    g_bsum);
    cudaGetSymbolAddress((void**)&bofs,    g_bofs);

    cudaFuncSetAttribute(gemm_infc,
        cudaFuncAttributeMaxDynamicSharedMemorySize, GEMM_SMEM);
    cudaFuncSetAttribute(gemm_tf32<true>,
        cudaFuncAttributeMaxDynamicSharedMemorySize, GEMM_SMEM);
    cudaFuncSetAttribute(gemm_tf32<false>,
        cudaFuncAttributeMaxDynamicSharedMemorySize, GEMM_SMEM);

    int gblocks = (N + 127) / 128;
    int eblocks = (E + 255) / 256;
    int ablocks = (N * 32 + 255) / 256;
    int sblocks = (N + 1023) / 1024;

    convert_w_kernel<<<(7 * D * D + 255) / 256, 256>>>(in_fc_w, w_rel, w_root, Wt);

    // CSR build (dst-sorted adjacency) with multi-block scan
    zero_int_kernel<<<(N + 255) / 256, 256>>>(cnt, N);
    hist_kernel<<<eblocks, 256>>>(dst, cnt, E);
    scan1_kernel<<<sblocks, 1024>>>(cnt, row_ptr, bsum, N);
    scan2_kernel<<<1, 64>>>(bsum, bofs, row_ptr, sblocks, N);
    scan3_kernel<<<sblocks, 1024>>>(row_ptr, cursor, bofs, N);
    fill_kernel<<<eblocks, 256>>>(src, dst, cursor, adj, E);

    // h = x @ in_fc_w + in_fc_b  (raw x; tf32 truncation inside mma path)
    gemm_infc<<<gblocks, 256, GEMM_SMEM>>>(x, Wt, in_fc_b, H, Ht, N);

    for (int l = 0; l < 3; l++) {
        aggregate_kernel<<<ablocks, 256>>>(H, row_ptr, adj, AGG, N);
        const float* W1 = Wt + (size_t)(1 + l) * D * D;
        const float* W2 = Wt + (size_t)(4 + l) * D * D;
        if (l < 2) {
            gemm_tf32<true><<<gblocks, 256, GEMM_SMEM>>>(
                AGG, W1, Ht, W2,
                b_rel + (size_t)l * D, H, H, Ht, N);
        } else {
            gemm_tf32<false><<<gblocks, 256, GEMM_SMEM>>>(
                AGG, W1, Ht, W2,
                b_rel + (size_t)l * D, H, (float*)d_out, nullptr, N);
        }
    }
}

// round 11
// speedup vs baseline: 2.4745x; 1.2616x over previous
#include <cuda_runtime.h>
#include <cuda_fp16.h>
#include <cstdint>

#define D 128
#define MAXN 50000
#define MAXE 800000

// Scratch (allocation-free)
__device__ float  g_H[MAXN * D];      // exact fp32 residual H
__device__ __half g_Ht[MAXN * D];     // fp16 H (GEMM A-operand + gather source)
__device__ __half g_AGG[MAXN * D];    // fp16 aggregate
__device__ __half g_Wh[7 * D * D];    // fp16 weights, transposed [n][k]
__device__ float  g_W32[D * D];       // tf32-rounded in_fc weight, transposed [n][k]
__device__ int g_cnt[MAXN];
__device__ int g_row_ptr[MAXN + 1];
__device__ int g_cursor[MAXN];
__device__ int g_adj[MAXE];
__device__ int g_bsum[64];
__device__ int g_bofs[64];

// ---------------- helpers ----------------

__device__ __forceinline__ float tf32r(float x) {
    uint32_t u;
    asm("cvt.rna.tf32.f32 %0, %1;" : "=r"(u) : "f"(x));
    return __uint_as_float(u);
}

__device__ __forceinline__ void mma_tf32(float* d,
    uint32_t a0, uint32_t a1, uint32_t a2, uint32_t a3,
    uint32_t b0, uint32_t b1)
{
    asm volatile(
        "mma.sync.aligned.m16n8k8.row.col.f32.tf32.tf32.f32 "
        "{%0,%1,%2,%3}, {%4,%5,%6,%7}, {%8,%9}, {%0,%1,%2,%3};\n"
        : "+f"(d[0]), "+f"(d[1]), "+f"(d[2]), "+f"(d[3])
        : "r"(a0), "r"(a1), "r"(a2), "r"(a3), "r"(b0), "r"(b1));
}

__device__ __forceinline__ void mma_f16(float* d,
    uint32_t a0, uint32_t a1, uint32_t a2, uint32_t a3,
    uint32_t b0, uint32_t b1)
{
    asm volatile(
        "mma.sync.aligned.m16n8k16.row.col.f32.f16.f16.f32 "
        "{%0,%1,%2,%3}, {%4,%5,%6,%7}, {%8,%9}, {%0,%1,%2,%3};\n"
        : "+f"(d[0]), "+f"(d[1]), "+f"(d[2]), "+f"(d[3])
        : "r"(a0), "r"(a1), "r"(a2), "r"(a3), "r"(b0), "r"(b1));
}

__device__ __forceinline__ void cp_async16(void* smem_p, const void* gmem, bool pred)
{
    uint32_t s = (uint32_t)__cvta_generic_to_shared(smem_p);
    int sz = pred ? 16 : 0;
    asm volatile("cp.async.cg.shared.global [%0], [%1], 16, %2;\n"
                 :: "r"(s), "l"(gmem), "r"(sz));
}
__device__ __forceinline__ void cp_commit() {
    asm volatile("cp.async.commit_group;\n");
}
template <int N_>
__device__ __forceinline__ void cp_wait() {
    asm volatile("cp.async.wait_group %0;\n" :: "n"(N_));
}

// ---------------- conversion ----------------

__global__ void __launch_bounds__(256) convert_w_kernel(
    const float* __restrict__ fw, const float* __restrict__ wrel,
    const float* __restrict__ wroot,
    __half* __restrict__ Wh, float* __restrict__ W32)
{
    int idx = blockIdx.x * 256 + threadIdx.x;
    if (idx >= 7 * D * D) return;
    int s = idx >> 14;
    int r = idx & 16383;
    int k = r >> 7;
    int n = r & 127;
    const float* srcm = (s == 0) ? fw
                      : (s < 4)  ? wrel + (size_t)(s - 1) * D * D
                                 : wroot + (size_t)(s - 4) * D * D;
    float v = srcm[k * D + n];
    Wh[(size_t)s * D * D + n * D + k] = __float2half(v);
    if (s == 0) W32[n * D + k] = tf32r(v);
}

// ---------------- CSR build ----------------

__global__ void __launch_bounds__(256) zero_int_kernel(int* __restrict__ p, int n) {
    int i = blockIdx.x * blockDim.x + threadIdx.x;
    for (; i < n; i += gridDim.x * blockDim.x) p[i] = 0;
}

__global__ void __launch_bounds__(256) hist_kernel(
    const int* __restrict__ dst, int* __restrict__ cnt, int E)
{
    int i = blockIdx.x * blockDim.x + threadIdx.x;
    for (; i < E; i += gridDim.x * blockDim.x)
        atomicAdd(&cnt[dst[i]], 1);
}

__global__ void __launch_bounds__(1024) scan1_kernel(
    const int* __restrict__ cnt, int* __restrict__ row_ptr,
    int* __restrict__ bsum, int n)
{
    __shared__ int warp_sums[32];
    int tid = threadIdx.x;
    int i = blockIdx.x * 1024 + tid;
    int lane = tid & 31, w = tid >> 5;

    int v = (i < n) ? cnt[i] : 0;
    int incl = v;
    #pragma unroll
    for (int o = 1; o < 32; o <<= 1) {
        int t = __shfl_up_sync(~0u, incl, o);
        if (lane >= o) incl += t;
    }
    if (lane == 31) warp_sums[w] = incl;
    __syncthreads();
    if (w == 0) {
        int s = warp_sums[lane];
        #pragma unroll
        for (int o = 1; o < 32; o <<= 1) {
            int t = __shfl_up_sync(~0u, s, o);
            if (lane >= o) s += t;
        }
        warp_sums[lane] = s;
    }
    __syncthreads();

    int excl = incl - v + (w > 0 ? warp_sums[w - 1] : 0);
    if (i < n) row_ptr[i] = excl;
    if (tid == 1023) bsum[blockIdx.x] = excl + v;
}

__global__ void __launch_bounds__(64) scan2_kernel(
    const int* __restrict__ bsum, int* __restrict__ bofs,
    int* __restrict__ row_ptr, int nblocks, int n)
{
    __shared__ int sh[64];
    int tid = threadIdx.x;
    sh[tid] = (tid < nblocks) ? bsum[tid] : 0;
    __syncthreads();
    if (tid == 0) {
        int run = 0;
        for (int b = 0; b < nblocks; b++) {
            bofs[b] = run;
            run += sh[b];
        }
        row_ptr[n] = run;
    }
}

__global__ void __launch_bounds__(1024) scan3_kernel(
    int* __restrict__ row_ptr, int* __restrict__ cursor,
    const int* __restrict__ bofs, int n)
{
    int i = blockIdx.x * 1024 + threadIdx.x;
    if (i >= n) return;
    int v = row_ptr[i] + bofs[blockIdx.x];
    row_ptr[i] = v;
    cursor[i] = v;
}

__global__ void __launch_bounds__(256) fill_kernel(
    const int* __restrict__ src, const int* __restrict__ dst,
    int* __restrict__ cursor, int* __restrict__ adj, int E)
{
    int i = blockIdx.x * blockDim.x + threadIdx.x;
    for (; i < E; i += gridDim.x * blockDim.x) {
        int p = atomicAdd(&cursor[dst[i]], 1);
        adj[p] = src[i];
    }
}

// ---------------- gather-aggregate (fp16 in/out, fp32 sums) ----------------

__global__ void __launch_bounds__(256) aggregate_kernel(
    const __half* __restrict__ Ht, const int* __restrict__ row_ptr,
    const int* __restrict__ adj, __half* __restrict__ AGG, int N)
{
    int node = (blockIdx.x * blockDim.x + threadIdx.x) >> 5;
    int lane = threadIdx.x & 31;
    if (node >= N) return;
    int beg = __ldg(row_ptr + node);
    int end = __ldg(row_ptr + node + 1);

    float4 acc = make_float4(0.f, 0.f, 0.f, 0.f);
    int e = beg;
    for (; e + 4 <= end; e += 4) {
        int s0 = __ldg(adj + e + 0);
        int s1 = __ldg(adj + e + 1);
        int s2 = __ldg(adj + e + 2);
        int s3 = __ldg(adj + e + 3);
        uint2 u0 = __ldg((const uint2*)(Ht + (size_t)s0 * D) + lane);
        uint2 u1 = __ldg((const uint2*)(Ht + (size_t)s1 * D) + lane);
        uint2 u2 = __ldg((const uint2*)(Ht + (size_t)s2 * D) + lane);
        uint2 u3 = __ldg((const uint2*)(Ht + (size_t)s3 * D) + lane);
        #pragma unroll
        for (int j = 0; j < 4; j++) {
            uint2 u = j == 0 ? u0 : j == 1 ? u1 : j == 2 ? u2 : u3;
            float2 lo = __half22float2(*(__half2*)&u.x);
            float2 hi = __half22float2(*(__half2*)&u.y);
            acc.x += lo.x; acc.y += lo.y; acc.z += hi.x; acc.w += hi.y;
        }
    }
    for (; e < end; e++) {
        int s = __ldg(adj + e);
        uint2 u = __ldg((const uint2*)(Ht + (size_t)s * D) + lane);
        float2 lo = __half22float2(*(__half2*)&u.x);
        float2 hi = __half22float2(*(__half2*)&u.y);
        acc.x += lo.x; acc.y += lo.y; acc.z += hi.x; acc.w += hi.y;
    }
    uint2 o;
    *(__half2*)&o.x = __floats2half2_rn(acc.x, acc.y);
    *(__half2*)&o.y = __floats2half2_rn(acc.z, acc.w);
    ((uint2*)(AGG + (size_t)node * D))[lane] = o;
}

// ---------------- in_fc GEMM (tf32, raw fp32 x) ----------------

#define SK 36
#define TILE_F (128 * SK)
#define STAGE_F (2 * TILE_F)
#define GEMM_SMEM (2 * STAGE_F * 4)

__global__ void __launch_bounds__(256, 2) gemm_infc(
    const float* __restrict__ A1, const float* __restrict__ W1,
    const float* __restrict__ bias,
    float* __restrict__ out, __half* __restrict__ OutRt, int N)
{
    extern __shared__ __align__(16) float sm[];

    int tid = threadIdx.x;
    int lane = tid & 31, w = tid >> 5;
    int warp_m = w & 3;
    int warp_n = w >> 2;
    int g = lane >> 2, tg = lane & 3;
    int row0 = blockIdx.x * 128;

    float acc[2][8][4];
    #pragma unroll
    for (int mf = 0; mf < 2; mf++)
        #pragma unroll
        for (int nf = 0; nf < 8; nf++)
            #pragma unroll
            for (int c = 0; c < 4; c++) acc[mf][nf][c] = 0.f;

    auto prefetch = [&](int c, int buf) {
        int koff = c * 32;
        float* base = sm + buf * STAGE_F;
        #pragma unroll
        for (int i = 0; i < 4; i++) {
            int idx = tid + i * 256;
            int r = idx >> 3, u = idx & 7;
            int gr = row0 + r;
            cp_async16(base + r * SK + u * 4,
                       A1 + (size_t)gr * D + koff + u * 4, gr < N);
            cp_async16(base + TILE_F + r * SK + u * 4,
                       W1 + (size_t)r * D + koff + u * 4, true);
        }
        cp_commit();
    };

    prefetch(0, 0);

    #pragma unroll 1
    for (int c = 0; c < 4; c++) {
        cp_wait<0>();
        __syncthreads();
        if (c + 1 < 4) prefetch(c + 1, (c + 1) & 1);

        const float* sa = sm + (c & 1) * STAGE_F;
        const float* sb = sa + TILE_F;

        #pragma unroll
        for (int ks = 0; ks < 4; ks++) {
            uint32_t bfr[8][2];
            #pragma unroll
            for (int nf = 0; nf < 8; nf++) {
                int n = warp_n * 64 + nf * 8 + g;
                bfr[nf][0] = __float_as_uint(sb[n * SK + ks * 8 + tg]);
                bfr[nf][1] = __float_as_uint(sb[n * SK + ks * 8 + tg + 4]);
            }
            #pragma unroll
            for (int mf = 0; mf < 2; mf++) {
                int r0 = warp_m * 32 + mf * 16 + g;
                uint32_t a0 = __float_as_uint(sa[r0 * SK + ks * 8 + tg]);
                uint32_t a1 = __float_as_uint(sa[(r0 + 8) * SK + ks * 8 + tg]);
                uint32_t a2 = __float_as_uint(sa[r0 * SK + ks * 8 + tg + 4]);
                uint32_t a3 = __float_as_uint(sa[(r0 + 8) * SK + ks * 8 + tg + 4]);
                #pragma unroll
                for (int nf = 0; nf < 8; nf++)
                    mma_tf32(acc[mf][nf], a0, a1, a2, a3,
                             bfr[nf][0], bfr[nf][1]);
            }
        }
    }

    __syncthreads();

    #pragma unroll
    for (int mf = 0; mf < 2; mf++) {
        #pragma unroll
        for (int half = 0; half < 2; half++) {
            int row = row0 + warp_m * 32 + mf * 16 + g + half * 8;
            if (row >= N) continue;
            #pragma unroll
            for (int nf = 0; nf < 8; nf++) {
                int col = warp_n * 64 + nf * 8 + tg * 2;
                float cx = acc[mf][nf][half * 2 + 0] + __ldg(bias + col);
                float cy = acc[mf][nf][half * 2 + 1] + __ldg(bias + col + 1);
                *(float2*)(out + (size_t)row * D + col) = make_float2(cx, cy);
                *(__half2*)(OutRt + (size_t)row * D + col) =
                    __floats2half2_rn(cx, cy);
            }
        }
    }
}

// ---------------- dual-term fp16 GEMM ----------------
// relu(AGG@W1 + Ht@W2 + bias) + H. Long-K: 8 chunks of 32 halfs.
// smem tile row = 40 halfs (32 data + 8 pad) = 80 B; u32 stride 20 (conflict-free).

#define SKH 40
#define TILE_H (128 * SKH)           // halfs per tile
#define STAGE_H (2 * TILE_H)
#define GEMM16_SMEM (2 * STAGE_H * 2)  // bytes = 2 stages * 2 tiles * 128*40*2

template <bool WRITE_RT>
__global__ void __launch_bounds__(256, 2) gemm_f16(
    const __half* __restrict__ A1, const __half* __restrict__ W1,
    const __half* __restrict__ A2, const __half* __restrict__ W2,
    const float* __restrict__ bias, const float* __restrict__ Hres,
    float* __restrict__ out, __half* __restrict__ OutRt, int N)
{
    extern __shared__ __align__(16) __half smh[];

    int tid = threadIdx.x;
    int lane = tid & 31, w = tid >> 5;
    int warp_m = w & 3;
    int warp_n = w >> 2;
    int g = lane >> 2, tg = lane & 3;
    int row0 = blockIdx.x * 128;

    float acc[2][8][4];
    #pragma unroll
    for (int mf = 0; mf < 2; mf++)
        #pragma unroll
        for (int nf = 0; nf < 8; nf++)
            #pragma unroll
            for (int c = 0; c < 4; c++) acc[mf][nf][c] = 0.f;

    auto prefetch = [&](int c, int buf) {
        int t = c >> 2;
        int koff = (c & 3) * 32;
        const __half* Ag = t ? A2 : A1;
        const __half* Bg = t ? W2 : W1;
        __half* base = smh + buf * STAGE_H;
        #pragma unroll
        for (int i = 0; i < 2; i++) {
            int idx = tid + i * 256;
            int r = idx >> 2, u = idx & 3;           // 4x16B units per 32-half row
            int gr = row0 + r;
            cp_async16(base + r * SKH + u * 8,
                       Ag + (size_t)gr * D + koff + u * 8, gr < N);
            cp_async16(base + TILE_H + r * SKH + u * 8,
                       Bg + (size_t)r * D + koff + u * 8, true);
        }
        cp_commit();
    };

    prefetch(0, 0);

    #pragma unroll 1
    for (int c = 0; c < 8; c++) {
        cp_wait<0>();
        __syncthreads();
        if (c + 1 < 8) prefetch(c + 1, (c + 1) & 1);

        const uint32_t* sa = (const uint32_t*)(smh + (c & 1) * STAGE_H);
        const uint32_t* sb = sa + TILE_H / 2;

        #pragma unroll
        for (int ks = 0; ks < 2; ks++) {
            uint32_t bfr[8][2];
            #pragma unroll
            for (int nf = 0; nf < 8; nf++) {
                int n = warp_n * 64 + nf * 8 + g;
                bfr[nf][0] = sb[n * 20 + ks * 8 + tg];
                bfr[nf][1] = sb[n * 20 + ks * 8 + tg + 4];
            }
            #pragma unroll
            for (int mf = 0; mf < 2; mf++) {
                int r0 = warp_m * 32 + mf * 16 + g;
                uint32_t a0 = sa[r0 * 20 + ks * 8 + tg];
                uint32_t a1 = sa[(r0 + 8) * 20 + ks * 8 + tg];
                uint32_t a2 = sa[r0 * 20 + ks * 8 + tg + 4];
                uint32_t a3 = sa[(r0 + 8) * 20 + ks * 8 + tg + 4];
                #pragma unroll
                for (int nf = 0; nf < 8; nf++)
                    mma_f16(acc[mf][nf], a0, a1, a2, a3,
                            bfr[nf][0], bfr[nf][1]);
            }
        }
    }

    __syncthreads();

    #pragma unroll
    for (int mf = 0; mf < 2; mf++) {
        #pragma unroll
        for (int half = 0; half < 2; half++) {
            int row = row0 + warp_m * 32 + mf * 16 + g + half * 8;
            if (row >= N) continue;
            #pragma unroll
            for (int nf = 0; nf < 8; nf++) {
                int col = warp_n * 64 + nf * 8 + tg * 2;
                float cx = acc[mf][nf][half * 2 + 0] + __ldg(bias + col);
                float cy = acc[mf][nf][half * 2 + 1] + __ldg(bias + col + 1);
                float2 h2 = *(const float2*)(Hres + (size_t)row * D + col);
                cx = fmaxf(cx, 0.f) + h2.x;
                cy = fmaxf(cy, 0.f) + h2.y;
                *(float2*)(out + (size_t)row * D + col) = make_float2(cx, cy);
                if (WRITE_RT) {
                    *(__half2*)(OutRt + (size_t)row * D + col) =
                        __floats2half2_rn(cx, cy);
                }
            }
        }
    }
}

// ---------------- launch ----------------

extern "C" void kernel_launch(void* const* d_in, const int* in_sizes, int n_in,
                              void* d_out, int out_size)
{
    const float* x       = (const float*)d_in[0];
    const int*   ei      = (const int*)  d_in[1];
    const float* in_fc_w = (const float*)d_in[2];
    const float* in_fc_b = (const float*)d_in[3];
    const float* w_rel   = (const float*)d_in[4];
    const float* b_rel   = (const float*)d_in[5];
    const float* w_root  = (const float*)d_in[6];

    int N = in_sizes[0] / D;
    int E = in_sizes[1] / 2;
    const int* src = ei;
    const int* dst = ei + E;

    float *H, *W32;
    __half *Ht, *AGG, *Wh;
    int *cnt, *row_ptr, *cursor, *adj, *bsum, *bofs;
    cudaGetSymbolAddress((void**)&H,       g_H);
    cudaGetSymbolAddress((void**)&Ht,      g_Ht);
    cudaGetSymbolAddress((void**)&AGG,     g_AGG);
    cudaGetSymbolAddress((void**)&Wh,      g_Wh);
    cudaGetSymbolAddress((void**)&W32,     g_W32);
    cudaGetSymbolAddress((void**)&cnt,     g_cnt);
    cudaGetSymbolAddress((void**)&row_ptr, g_row_ptr);
    cudaGetSymbolAddress((void**)&cursor,  g_cursor);
    cudaGetSymbolAddress((void**)&adj,     g_adj);
    cudaGetSymbolAddress((void**)&bsum,    g_bsum);
    cudaGetSymbolAddress((void**)&bofs,    g_bofs);

    cudaFuncSetAttribute(gemm_infc,
        cudaFuncAttributeMaxDynamicSharedMemorySize, GEMM_SMEM);
    cudaFuncSetAttribute(gemm_f16<true>,
        cudaFuncAttributeMaxDynamicSharedMemorySize, GEMM16_SMEM);
    cudaFuncSetAttribute(gemm_f16<false>,
        cudaFuncAttributeMaxDynamicSharedMemorySize, GEMM16_SMEM);

    int gblocks = (N + 127) / 128;
    int eblocks = (E + 255) / 256;
    int ablocks = (N * 32 + 255) / 256;
    int sblocks = (N + 1023) / 1024;

    convert_w_kernel<<<(7 * D * D + 255) / 256, 256>>>(in_fc_w, w_rel, w_root, Wh, W32);

    // CSR build (dst-sorted adjacency), multi-block scan
    zero_int_kernel<<<(N + 255) / 256, 256>>>(cnt, N);
    hist_kernel<<<eblocks, 256>>>(dst, cnt, E);
    scan1_kernel<<<sblocks, 1024>>>(cnt, row_ptr, bsum, N);
    scan2_kernel<<<1, 64>>>(bsum, bofs, row_ptr, sblocks, N);
    scan3_kernel<<<sblocks, 1024>>>(row_ptr, cursor, bofs, N);
    fill_kernel<<<eblocks, 256>>>(src, dst, cursor, adj, E);

    // h = x @ in_fc_w + in_fc_b  (tf32; writes H fp32 + Ht fp16)
    gemm_infc<<<gblocks, 256, GEMM_SMEM>>>(x, W32, in_fc_b, H, Ht, N);

    for (int l = 0; l < 3; l++) {
        aggregate_kernel<<<ablocks, 256>>>(Ht, row_ptr, adj, AGG, N);
        const __half* W1 = Wh + (size_t)(1 + l) * D * D;
        const __half* W2 = Wh + (size_t)(4 + l) * D * D;
        if (l < 2) {
            gemm_f16<true><<<gblocks, 256, GEMM16_SMEM>>>(
                AGG, W1, Ht, W2,
                b_rel + (size_t)l * D, H, H, Ht, N);
        } else {
            gemm_f16<false><<<gblocks, 256, GEMM16_SMEM>>>(
                AGG, W1, Ht, W2,
                b_rel + (size_t)l * D, H, (float*)d_out, nullptr, N);
        }
    }
}